// round 1
// baseline (speedup 1.0000x reference)
#include <cuda_runtime.h>
#include <cuda_bf16.h>
#include <math.h>

// Problem constants (fixed for this dataset)
#define NNODES 50000
#define MAXE   262144
#define DDIM   128
#define HDIM   256
#define NEXP   4

// ---------------- device scratch (static allocation only) ----------------
__device__ int   g_counts[NEXP];
__device__ int   g_flag64;
__device__ int   g_bucket[NEXP][MAXE];      // 4 MB
__device__ float g_topv[MAXE];              // 1 MB
__device__ float g_partial[4096][NEXP];     // per gate-block prob sums

// ---------------- kernel 0: init + index dtype sniff ----------------
__global__ void k_init(const void* uptr) {
    if (threadIdx.x < NEXP) g_counts[threadIdx.x] = 0;
    if (threadIdx.x == 0) {
        // If u is int64 (little endian) the high 32-bit words are all zero
        // (values < 50000). If it is int32, odd words are u[1],u[3],... which
        // are ~uniform in [0,50000) -> essentially never all zero over 64 samples.
        const int* p = (const int*)uptr;
        int is64 = 1;
        #pragma unroll 1
        for (int i = 0; i < 64; i++) {
            if (p[2 * i + 1] != 0) { is64 = 0; break; }
        }
        g_flag64 = is64;
    }
}

// ---------------- kernel 1: gate (softmax + top-1 + bucketing) ----------------
// block = 256 threads (8 warps), each warp processes 8 edges -> 64 edges/block
__global__ __launch_bounds__(256) void k_gate(
    const float* __restrict__ z,
    const void*  __restrict__ u_, const void* __restrict__ v_,
    const float* __restrict__ gate_w,   // [512,4] row-major
    const float* __restrict__ gate_b,   // [4]
    int E)
{
    __shared__ __align__(16) float sgw[512 * 4];
    __shared__ float wpart[8][NEXP];

    const int tid  = threadIdx.x;
    const int warp = tid >> 5;
    const int lane = tid & 31;

    for (int t = tid; t < 2048; t += 256) sgw[t] = gate_w[t];
    __syncthreads();

    const int flag64 = g_flag64;
    const float4* gw4 = reinterpret_cast<const float4*>(sgw);

    float p0 = 0.f, p1 = 0.f, p2 = 0.f, p3 = 0.f;   // lane-0 prob sums

    #pragma unroll 1
    for (int t = 0; t < 8; t++) {
        const int e = (int)blockIdx.x * 64 + warp * 8 + t;
        if (e >= E) break;

        int uu, vv;
        if (flag64) {
            uu = (int)((const long long*)u_)[e];
            vv = (int)((const long long*)v_)[e];
        } else {
            uu = ((const int*)u_)[e];
            vv = ((const int*)v_)[e];
        }
        const float* zu = z + (size_t)uu * DDIM;
        const float* zv = z + (size_t)vv * DDIM;

        float g0 = 0.f, g1 = 0.f, g2 = 0.f, g3 = 0.f;
        #pragma unroll
        for (int kk = 0; kk < 4; kk++) {
            const int k = lane + kk * 32;
            const float a = zu[k];
            const float b = zv[k];
            const float d = fabsf(a - b);
            const float m = a * b;
            const float4 wA = gw4[k];
            const float4 wB = gw4[128 + k];
            const float4 wD = gw4[256 + k];
            const float4 wM = gw4[384 + k];
            g0 += a * wA.x + b * wB.x + d * wD.x + m * wM.x;
            g1 += a * wA.y + b * wB.y + d * wD.y + m * wM.y;
            g2 += a * wA.z + b * wB.z + d * wD.z + m * wM.z;
            g3 += a * wA.w + b * wB.w + d * wD.w + m * wM.w;
        }
        #pragma unroll
        for (int off = 16; off; off >>= 1) {
            g0 += __shfl_xor_sync(0xffffffffu, g0, off);
            g1 += __shfl_xor_sync(0xffffffffu, g1, off);
            g2 += __shfl_xor_sync(0xffffffffu, g2, off);
            g3 += __shfl_xor_sync(0xffffffffu, g3, off);
        }

        if (lane == 0) {
            float l[NEXP];
            l[0] = g0 + gate_b[0]; l[1] = g1 + gate_b[1];
            l[2] = g2 + gate_b[2]; l[3] = g3 + gate_b[3];
            float mx = l[0];
            #pragma unroll
            for (int j = 1; j < NEXP; j++) mx = fmaxf(mx, l[j]);
            float ex[NEXP]; float s = 0.f;
            #pragma unroll
            for (int j = 0; j < NEXP; j++) { ex[j] = expf(l[j] - mx); s += ex[j]; }
            const float inv = 1.f / s;
            float pr[NEXP];
            #pragma unroll
            for (int j = 0; j < NEXP; j++) pr[j] = ex[j] * inv;
            // argmax (first max -> matches jax top_k tie-breaking)
            int arg = 0; float best = pr[0];
            #pragma unroll
            for (int j = 1; j < NEXP; j++) if (pr[j] > best) { best = pr[j]; arg = j; }

            g_topv[e] = best;
            const int pos = atomicAdd(&g_counts[arg], 1);
            g_bucket[arg][pos] = e;

            p0 += pr[0]; p1 += pr[1]; p2 += pr[2]; p3 += pr[3];
        }
    }

    if (lane == 0) {
        wpart[warp][0] = p0; wpart[warp][1] = p1;
        wpart[warp][2] = p2; wpart[warp][3] = p3;
    }
    __syncthreads();
    if (tid < NEXP) {
        float s = 0.f;
        #pragma unroll
        for (int w = 0; w < 8; w++) s += wpart[w][tid];
        g_partial[blockIdx.x][tid] = s;
    }
}

// ---------------- kernels 2-5: fused expert MLPs ----------------
// MODE: 0 = cat [zu,zv] K=256; 1 = dist |zu-zv| K=128; 2 = mul zu*zv K=128;
//       3 = all [zu,zv,|diff|,mul] K=512
// Tile: 64 edges per block, 256 threads, thread = (ty,tx) 16x16,
// micro-tile 4 edges x 4 hidden.
#define XSTRIDE 68   // 68*4 bytes = 272, multiple of 16 -> aligned float4 rows

template <int K, int MODE>
__global__ __launch_bounds__(256) void k_expert(
    const float* __restrict__ z,
    const void*  __restrict__ u_, const void* __restrict__ v_,
    const float* __restrict__ w1,  // [K,256]
    const float* __restrict__ b1,  // [256]
    const float* __restrict__ w2,  // [256,1]
    const float* __restrict__ b2,  // [1]
    float* __restrict__ out,
    int expert)
{
    extern __shared__ __align__(16) float sm[];
    float* XT  = sm;                    // [K][XSTRIDE] transposed features
    float* Wsm = XT + K * XSTRIDE;      // [32][64]
    float* sb1 = Wsm + 2048;            // [256]
    float* sw2 = sb1 + 256;             // [256]
    float* red = sw2 + 256;             // [64][16]
    float* stv = red + 1024;            // [64]
    int*   se  = (int*)(stv + 64);      // [64]
    int*   su  = se + 64;               // [64]
    int*   sv  = su + 64;               // [64]

    const int tid = threadIdx.x;
    const int tx  = tid & 15;           // hidden group
    const int ty  = tid >> 4;           // edge group
    const int tx4 = tx * 4;
    const int ty4 = ty * 4;

    if (tid < 256) { sb1[tid] = b1[tid]; sw2[tid] = w2[tid]; }
    const float b2s = b2[0];
    const int flag64 = g_flag64;
    const int count  = g_counts[expert];
    const int ntiles = (count + 63) >> 6;

    for (int tile = blockIdx.x; tile < ntiles; tile += gridDim.x) {
        __syncthreads();   // protect smem reuse across tiles
        const int base = tile * 64;
        const int nE   = min(64, count - base);

        if (tid < 64) {
            int e = (tid < nE) ? g_bucket[expert][base + tid] : -1;
            se[tid]  = e;
            stv[tid] = (e >= 0) ? g_topv[e] : 0.f;
            int uu = 0, vv = 0;
            if (e >= 0) {
                if (flag64) {
                    uu = (int)((const long long*)u_)[e];
                    vv = (int)((const long long*)v_)[e];
                } else {
                    uu = ((const int*)u_)[e];
                    vv = ((const int*)v_)[e];
                }
            }
            su[tid] = uu; sv[tid] = vv;
        }
        __syncthreads();

        // Build transposed feature tile XT[k][edge]
        #pragma unroll 1
        for (int idx = tid; idx < 64 * DDIM; idx += 256) {
            const int i = idx >> 7;          // edge in tile
            const int k = idx & 127;         // feature dim within D
            float a = z[(size_t)su[i] * DDIM + k];
            float b = z[(size_t)sv[i] * DDIM + k];
            if (se[i] < 0) { a = 0.f; b = 0.f; }
            if (MODE == 0) {            // cat
                XT[k * XSTRIDE + i]           = a;
                XT[(128 + k) * XSTRIDE + i]   = b;
            } else if (MODE == 1) {     // dist
                XT[k * XSTRIDE + i] = fabsf(a - b);
            } else if (MODE == 2) {     // mul
                XT[k * XSTRIDE + i] = a * b;
            } else {                    // all
                XT[k * XSTRIDE + i]           = a;
                XT[(128 + k) * XSTRIDE + i]   = b;
                XT[(256 + k) * XSTRIDE + i]   = fabsf(a - b);
                XT[(384 + k) * XSTRIDE + i]   = a * b;
            }
        }

        float sc0 = 0.f, sc1 = 0.f, sc2 = 0.f, sc3 = 0.f;

        #pragma unroll 1
        for (int hb = 0; hb < HDIM; hb += 64) {
            float acc[4][4];
            #pragma unroll
            for (int i = 0; i < 4; i++)
                #pragma unroll
                for (int j = 0; j < 4; j++) acc[i][j] = 0.f;

            #pragma unroll 1
            for (int kb = 0; kb < K; kb += 32) {
                __syncthreads();
                for (int t = tid; t < 2048; t += 256) {
                    const int r = t >> 6, c = t & 63;
                    Wsm[t] = w1[(size_t)(kb + r) * HDIM + hb + c];
                }
                __syncthreads();
                #pragma unroll
                for (int r = 0; r < 32; r++) {
                    const float4 wv = *reinterpret_cast<const float4*>(&Wsm[r * 64 + tx4]);
                    const float4 xv = *reinterpret_cast<const float4*>(&XT[(kb + r) * XSTRIDE + ty4]);
                    acc[0][0] += xv.x * wv.x; acc[0][1] += xv.x * wv.y;
                    acc[0][2] += xv.x * wv.z; acc[0][3] += xv.x * wv.w;
                    acc[1][0] += xv.y * wv.x; acc[1][1] += xv.y * wv.y;
                    acc[1][2] += xv.y * wv.z; acc[1][3] += xv.y * wv.w;
                    acc[2][0] += xv.z * wv.x; acc[2][1] += xv.z * wv.y;
                    acc[2][2] += xv.z * wv.z; acc[2][3] += xv.z * wv.w;
                    acc[3][0] += xv.w * wv.x; acc[3][1] += xv.w * wv.y;
                    acc[3][2] += xv.w * wv.z; acc[3][3] += xv.w * wv.w;
                }
            }
            // fused relu + layer-2 dot
            #pragma unroll
            for (int j = 0; j < 4; j++) {
                const float bb = sb1[hb + tx4 + j];
                const float ww = sw2[hb + tx4 + j];
                sc0 += fmaxf(acc[0][j] + bb, 0.f) * ww;
                sc1 += fmaxf(acc[1][j] + bb, 0.f) * ww;
                sc2 += fmaxf(acc[2][j] + bb, 0.f) * ww;
                sc3 += fmaxf(acc[3][j] + bb, 0.f) * ww;
            }
        }

        __syncthreads();
        red[(ty4 + 0) * 16 + tx] = sc0;
        red[(ty4 + 1) * 16 + tx] = sc1;
        red[(ty4 + 2) * 16 + tx] = sc2;
        red[(ty4 + 3) * 16 + tx] = sc3;
        __syncthreads();

        if (tid < 64 && se[tid] >= 0) {
            float s = 0.f;
            #pragma unroll
            for (int t = 0; t < 16; t++) s += red[tid * 16 + t];
            out[se[tid]] = stv[tid] * (s + b2s);
        }
    }
}

// ---------------- kernel 6: aux loss reduction (deterministic) ----------------
__global__ __launch_bounds__(256) void k_aux(float* out, int out_size, int nblocks, int E)
{
    __shared__ float s[256];
    float acc[NEXP] = {0.f, 0.f, 0.f, 0.f};
    for (int i = threadIdx.x; i < nblocks; i += 256) {
        #pragma unroll
        for (int j = 0; j < NEXP; j++) acc[j] += g_partial[i][j];
    }
    float tot[NEXP];
    #pragma unroll
    for (int j = 0; j < NEXP; j++) {
        s[threadIdx.x] = acc[j];
        __syncthreads();
        for (int st = 128; st; st >>= 1) {
            if (threadIdx.x < st) s[threadIdx.x] += s[threadIdx.x + st];
            __syncthreads();
        }
        tot[j] = s[0];
        __syncthreads();
    }
    if (threadIdx.x == 0 && out_size > E) {
        float aux = 0.f;
        const float invE = 1.f / (float)E;
        #pragma unroll
        for (int j = 0; j < NEXP; j++) {
            const float m = tot[j] * invE;
            aux += m * m;
        }
        out[E] = aux * (float)NEXP;
    }
}

// ---------------- host launcher ----------------
static inline size_t smem_bytes(int K) {
    return (size_t)(K * XSTRIDE + 2048 + 256 + 256 + 1024 + 64 + 64 + 64 + 64) * 4;
}

extern "C" void kernel_launch(void* const* d_in, const int* in_sizes, int n_in,
                              void* d_out, int out_size)
{
    const float* z       = (const float*)d_in[0];
    const void*  u       = d_in[1];
    const void*  v       = d_in[2];
    const float* gate_w  = (const float*)d_in[3];
    const float* gate_b  = (const float*)d_in[4];
    const float* cat_w1  = (const float*)d_in[5];
    const float* cat_b1  = (const float*)d_in[6];
    const float* cat_w2  = (const float*)d_in[7];
    const float* cat_b2  = (const float*)d_in[8];
    const float* dist_w1 = (const float*)d_in[9];
    const float* dist_b1 = (const float*)d_in[10];
    const float* dist_w2 = (const float*)d_in[11];
    const float* dist_b2 = (const float*)d_in[12];
    const float* mul_w1  = (const float*)d_in[13];
    const float* mul_b1  = (const float*)d_in[14];
    const float* mul_w2  = (const float*)d_in[15];
    const float* mul_w2b = (const float*)d_in[16];
    const float* all_w1  = (const float*)d_in[17];
    const float* all_b1  = (const float*)d_in[18];
    const float* all_w2  = (const float*)d_in[19];
    const float* all_b2  = (const float*)d_in[20];
    float* out = (float*)d_out;

    const int E = in_sizes[1];                 // 262144
    const int gateBlocks = (E + 63) / 64;      // 4096

    // opt-in shared memory (idempotent every call; legal host API, no allocs)
    cudaFuncSetAttribute(k_expert<256, 0>, cudaFuncAttributeMaxDynamicSharedMemorySize, (int)smem_bytes(256));
    cudaFuncSetAttribute(k_expert<128, 1>, cudaFuncAttributeMaxDynamicSharedMemorySize, (int)smem_bytes(128));
    cudaFuncSetAttribute(k_expert<128, 2>, cudaFuncAttributeMaxDynamicSharedMemorySize, (int)smem_bytes(128));
    cudaFuncSetAttribute(k_expert<512, 3>, cudaFuncAttributeMaxDynamicSharedMemorySize, (int)smem_bytes(512));

    k_init<<<1, 256>>>(u);
    k_gate<<<gateBlocks, 256>>>(z, u, v, gate_w, gate_b, E);

    k_expert<256, 0><<<1024, 256, smem_bytes(256)>>>(z, u, v, cat_w1,  cat_b1,  cat_w2,  cat_b2,  out, 0);
    k_expert<128, 1><<<1024, 256, smem_bytes(128)>>>(z, u, v, dist_w1, dist_b1, dist_w2, dist_b2, out, 1);
    k_expert<128, 2><<<1024, 256, smem_bytes(128)>>>(z, u, v, mul_w1,  mul_b1,  mul_w2,  mul_w2b, out, 2);
    k_expert<512, 3><<<1024, 256, smem_bytes(512)>>>(z, u, v, all_w1,  all_b1,  all_w2,  all_b2,  out, 3);

    k_aux<<<1, 256>>>(out, out_size, gateBlocks, E);
}

// round 2
// speedup vs baseline: 1.4649x; 1.4649x over previous
#include <cuda_runtime.h>
#include <cuda_bf16.h>
#include <math.h>
#include <stdint.h>

// Problem constants (fixed for this dataset)
#define NNODES 50000
#define MAXE   262144
#define DDIM   128
#define HDIM   256
#define NEXP   4

// ---------------- device scratch (static allocation only) ----------------
__device__ int   g_counts[NEXP];
__device__ int   g_flag64;
__device__ int   g_bucket[NEXP][MAXE];      // 4 MB
__device__ float g_topv[MAXE];              // 1 MB
__device__ float g_partial[4096][NEXP];     // per gate-block prob sums

// ---------------- helpers: tf32 split + mma ----------------
__device__ __forceinline__ uint32_t f2tf32(float x) {
    uint32_t r;
    asm("cvt.rna.tf32.f32 %0, %1;" : "=r"(r) : "f"(x));
    return r;
}

__device__ __forceinline__ void split_tf32(float x, float& hi, float& lo) {
    uint32_t h = f2tf32(x);
    hi = __uint_as_float(h);
    lo = __uint_as_float(f2tf32(x - hi));
}

__device__ __forceinline__ void mma_tf32(float c[4],
                                         uint32_t a0, uint32_t a1, uint32_t a2, uint32_t a3,
                                         uint32_t b0, uint32_t b1) {
    asm volatile(
        "mma.sync.aligned.m16n8k8.row.col.f32.tf32.tf32.f32 "
        "{%0,%1,%2,%3}, {%4,%5,%6,%7}, {%8,%9}, {%0,%1,%2,%3};"
        : "+f"(c[0]), "+f"(c[1]), "+f"(c[2]), "+f"(c[3])
        : "r"(a0), "r"(a1), "r"(a2), "r"(a3), "r"(b0), "r"(b1));
}

// ---------------- kernel 0: init + index dtype sniff ----------------
__global__ void k_init(const void* uptr) {
    if (threadIdx.x < NEXP) g_counts[threadIdx.x] = 0;
    if (threadIdx.x == 0) {
        const int* p = (const int*)uptr;
        int is64 = 1;
        #pragma unroll 1
        for (int i = 0; i < 64; i++) {
            if (p[2 * i + 1] != 0) { is64 = 0; break; }
        }
        g_flag64 = is64;
    }
}

// ---------------- kernel 1: gate (softmax + top-1 + bucketing) ----------------
__global__ __launch_bounds__(256) void k_gate(
    const float* __restrict__ z,
    const void*  __restrict__ u_, const void* __restrict__ v_,
    const float* __restrict__ gate_w,   // [512,4] row-major
    const float* __restrict__ gate_b,   // [4]
    int E)
{
    __shared__ __align__(16) float sgw[512 * 4];
    __shared__ float wpart[8][NEXP];

    const int tid  = threadIdx.x;
    const int warp = tid >> 5;
    const int lane = tid & 31;

    for (int t = tid; t < 2048; t += 256) sgw[t] = gate_w[t];
    __syncthreads();

    const int flag64 = g_flag64;
    const float4* gw4 = reinterpret_cast<const float4*>(sgw);

    float p0 = 0.f, p1 = 0.f, p2 = 0.f, p3 = 0.f;

    #pragma unroll 1
    for (int t = 0; t < 8; t++) {
        const int e = (int)blockIdx.x * 64 + warp * 8 + t;
        if (e >= E) break;

        int uu, vv;
        if (flag64) {
            uu = (int)((const long long*)u_)[e];
            vv = (int)((const long long*)v_)[e];
        } else {
            uu = ((const int*)u_)[e];
            vv = ((const int*)v_)[e];
        }
        const float* zu = z + (size_t)uu * DDIM;
        const float* zv = z + (size_t)vv * DDIM;

        float g0 = 0.f, g1 = 0.f, g2 = 0.f, g3 = 0.f;
        #pragma unroll
        for (int kk = 0; kk < 4; kk++) {
            const int k = lane + kk * 32;
            const float a = zu[k];
            const float b = zv[k];
            const float d = fabsf(a - b);
            const float m = a * b;
            const float4 wA = gw4[k];
            const float4 wB = gw4[128 + k];
            const float4 wD = gw4[256 + k];
            const float4 wM = gw4[384 + k];
            g0 += a * wA.x + b * wB.x + d * wD.x + m * wM.x;
            g1 += a * wA.y + b * wB.y + d * wD.y + m * wM.y;
            g2 += a * wA.z + b * wB.z + d * wD.z + m * wM.z;
            g3 += a * wA.w + b * wB.w + d * wD.w + m * wM.w;
        }
        #pragma unroll
        for (int off = 16; off; off >>= 1) {
            g0 += __shfl_xor_sync(0xffffffffu, g0, off);
            g1 += __shfl_xor_sync(0xffffffffu, g1, off);
            g2 += __shfl_xor_sync(0xffffffffu, g2, off);
            g3 += __shfl_xor_sync(0xffffffffu, g3, off);
        }

        if (lane == 0) {
            float l[NEXP];
            l[0] = g0 + gate_b[0]; l[1] = g1 + gate_b[1];
            l[2] = g2 + gate_b[2]; l[3] = g3 + gate_b[3];
            float mx = l[0];
            #pragma unroll
            for (int j = 1; j < NEXP; j++) mx = fmaxf(mx, l[j]);
            float ex[NEXP]; float s = 0.f;
            #pragma unroll
            for (int j = 0; j < NEXP; j++) { ex[j] = expf(l[j] - mx); s += ex[j]; }
            const float inv = 1.f / s;
            float pr[NEXP];
            #pragma unroll
            for (int j = 0; j < NEXP; j++) pr[j] = ex[j] * inv;
            int arg = 0; float best = pr[0];
            #pragma unroll
            for (int j = 1; j < NEXP; j++) if (pr[j] > best) { best = pr[j]; arg = j; }

            g_topv[e] = best;
            const int pos = atomicAdd(&g_counts[arg], 1);
            g_bucket[arg][pos] = e;

            p0 += pr[0]; p1 += pr[1]; p2 += pr[2]; p3 += pr[3];
        }
    }

    if (lane == 0) {
        wpart[warp][0] = p0; wpart[warp][1] = p1;
        wpart[warp][2] = p2; wpart[warp][3] = p3;
    }
    __syncthreads();
    if (tid < NEXP) {
        float s = 0.f;
        #pragma unroll
        for (int w = 0; w < 8; w++) s += wpart[w][tid];
        g_partial[blockIdx.x][tid] = s;
    }
}

// ---------------- kernels 2-5: fused expert MLPs (tensor-core tf32x3) ------
// MODE: 0 = cat [zu,zv] K=256; 1 = dist K=128; 2 = mul K=128; 3 = all K=512
// Block: 256 threads = 8 warps. Tile: 64 edges x 256 hidden.
// Warp w -> hidden cols [w*32, w*32+32): 4 m-tiles (16 edges) x 4 n-tiles (8 cols)
// of mma.m16n8k8.tf32 with 3xTF32 split for fp32-grade accuracy.
// K streamed in KC=16 chunks, register-prefetched one chunk ahead.

#define KC      16
#define XSTR    72    // (72 mod 32)==8 -> fragment banks 8k+e: conflict-free
#define WSTR    264   // (264 mod 32)==8 -> fragment banks 8k+n: conflict-free

template <int K, int MODE>
__global__ __launch_bounds__(256, 2) void k_expert(
    const float* __restrict__ z,
    const void*  __restrict__ u_, const void* __restrict__ v_,
    const float* __restrict__ w1,  // [K,256]
    const float* __restrict__ b1,  // [256]
    const float* __restrict__ w2,  // [256,1]
    const float* __restrict__ b2,  // [1]
    float* __restrict__ out,
    int expert)
{
    __shared__ __align__(16) float sXhi[KC * XSTR];
    __shared__ __align__(16) float sXlo[KC * XSTR];
    __shared__ __align__(16) float sWhi[KC * WSTR];
    __shared__ __align__(16) float sWlo[KC * WSTR];
    __shared__ float sb1[HDIM];
    __shared__ float sw2[HDIM];
    __shared__ float red[64][8];
    __shared__ float stv[64];
    __shared__ int   se[64];
    __shared__ int   su[64];
    __shared__ int   sv[64];

    const int tid  = threadIdx.x;
    const int warp = tid >> 5;
    const int lane = tid & 31;
    const int lq   = lane & 3;       // quad index (k / col-pair)
    const int lg   = lane >> 2;      // group id (row / n-col)

    if (tid < HDIM) { sb1[tid] = b1[tid]; sw2[tid] = w2[tid]; }
    const float b2s    = b2[0];
    const int   flag64 = g_flag64;
    const int   count  = g_counts[expert];
    const int   ntiles = (count + 63) >> 6;
    constexpr int NCH  = K / KC;

    // W-prefetch indices: thread covers 4 of 1024 float4 slots per chunk
    int wr[4], wc[4];
    #pragma unroll
    for (int i = 0; i < 4; i++) {
        const int idx = tid + i * 256;
        wr[i] = idx >> 6;
        wc[i] = (idx & 63) << 2;
    }
    // X-prefetch indices: thread covers edge e, 4 feature dims starting j*4
    const int xe = tid >> 2;
    const int xj = (tid & 3) << 2;

    for (int tile = blockIdx.x; tile < ntiles; tile += gridDim.x) {
        __syncthreads();   // smem reuse guard across tiles
        const int base = tile * 64;
        const int nE   = min(64, count - base);

        if (tid < 64) {
            int e = (tid < nE) ? g_bucket[expert][base + tid] : -1;
            se[tid]  = e;
            stv[tid] = (e >= 0) ? g_topv[e] : 0.f;
            int uu = 0, vv = 0;
            if (e >= 0) {
                if (flag64) {
                    uu = (int)((const long long*)u_)[e];
                    vv = (int)((const long long*)v_)[e];
                } else {
                    uu = ((const int*)u_)[e];
                    vv = ((const int*)v_)[e];
                }
            }
            su[tid] = uu; sv[tid] = vv;
        }
        __syncthreads();

        // accumulators: 4 m-tiles x 4 n-tiles x 4 regs
        float acc[4][4][4];
        #pragma unroll
        for (int m = 0; m < 4; m++)
            #pragma unroll
            for (int n = 0; n < 4; n++)
                #pragma unroll
                for (int q = 0; q < 4; q++) acc[m][n][q] = 0.f;

        // ---- prefetch chunk 0 into regs ----
        float4 wv[4], xa, xb;
        {
            #pragma unroll
            for (int i = 0; i < 4; i++)
                wv[i] = *reinterpret_cast<const float4*>(w1 + (size_t)wr[i] * HDIM + wc[i]);
            const int d0 = 0;
            xa = *reinterpret_cast<const float4*>(z + (size_t)su[xe] * DDIM + d0 + xj);
            xb = *reinterpret_cast<const float4*>(z + (size_t)sv[xe] * DDIM + d0 + xj);
        }

        #pragma unroll 1
        for (int cb = 0; cb < NCH; cb++) {
            const int kb   = cb * KC;
            const int type = kb >> 7;       // which feature block (for MODE 0/3)

            __syncthreads();   // previous chunk compute finished

            // ---- store prefetched regs to smem (with tf32 split) ----
            #pragma unroll
            for (int i = 0; i < 4; i++) {
                const float wvv[4] = { wv[i].x, wv[i].y, wv[i].z, wv[i].w };
                #pragma unroll
                for (int c = 0; c < 4; c++) {
                    float hi, lo;
                    split_tf32(wvv[c], hi, lo);
                    sWhi[wr[i] * WSTR + wc[i] + c] = hi;
                    sWlo[wr[i] * WSTR + wc[i] + c] = lo;
                }
            }
            {
                const float av[4] = { xa.x, xa.y, xa.z, xa.w };
                const float bv[4] = { xb.x, xb.y, xb.z, xb.w };
                #pragma unroll
                for (int i = 0; i < 4; i++) {
                    float val;
                    if (MODE == 0)      val = (type == 0) ? av[i] : bv[i];
                    else if (MODE == 1) val = fabsf(av[i] - bv[i]);
                    else if (MODE == 2) val = av[i] * bv[i];
                    else {
                        if (type == 0)      val = av[i];
                        else if (type == 1) val = bv[i];
                        else if (type == 2) val = fabsf(av[i] - bv[i]);
                        else                val = av[i] * bv[i];
                    }
                    float hi, lo;
                    split_tf32(val, hi, lo);
                    sXhi[(xj + i) * XSTR + xe] = hi;
                    sXlo[(xj + i) * XSTR + xe] = lo;
                }
            }
            __syncthreads();

            // ---- prefetch next chunk while computing this one ----
            if (cb + 1 < NCH) {
                const int kb2 = kb + KC;
                #pragma unroll
                for (int i = 0; i < 4; i++)
                    wv[i] = *reinterpret_cast<const float4*>(
                        w1 + (size_t)(kb2 + wr[i]) * HDIM + wc[i]);
                const int d0 = kb2 & 127;
                xa = *reinterpret_cast<const float4*>(z + (size_t)su[xe] * DDIM + d0 + xj);
                xb = *reinterpret_cast<const float4*>(z + (size_t)sv[xe] * DDIM + d0 + xj);
            }

            // ---- tensor-core compute: 2 sub-chunks of k8 ----
            #pragma unroll
            for (int k8 = 0; k8 < 2; k8++) {
                const int kr   = k8 * 8 + lq;
                const int ncol = warp * 32 + lg;

                uint32_t bh[4][2], bl[4][2];
                #pragma unroll
                for (int n = 0; n < 4; n++) {
                    const int wi = kr * WSTR + ncol + n * 8;
                    bh[n][0] = __float_as_uint(sWhi[wi]);
                    bh[n][1] = __float_as_uint(sWhi[wi + 4 * WSTR]);
                    bl[n][0] = __float_as_uint(sWlo[wi]);
                    bl[n][1] = __float_as_uint(sWlo[wi + 4 * WSTR]);
                }

                #pragma unroll
                for (int m = 0; m < 4; m++) {
                    const int er = m * 16 + lg;
                    const int xi = kr * XSTR + er;
                    const uint32_t ah0 = __float_as_uint(sXhi[xi]);
                    const uint32_t ah1 = __float_as_uint(sXhi[xi + 8]);
                    const uint32_t ah2 = __float_as_uint(sXhi[xi + 4 * XSTR]);
                    const uint32_t ah3 = __float_as_uint(sXhi[xi + 4 * XSTR + 8]);
                    const uint32_t al0 = __float_as_uint(sXlo[xi]);
                    const uint32_t al1 = __float_as_uint(sXlo[xi + 8]);
                    const uint32_t al2 = __float_as_uint(sXlo[xi + 4 * XSTR]);
                    const uint32_t al3 = __float_as_uint(sXlo[xi + 4 * XSTR + 8]);

                    #pragma unroll
                    for (int n = 0; n < 4; n++) {
                        mma_tf32(acc[m][n], ah0, ah1, ah2, ah3, bl[n][0], bl[n][1]);
                        mma_tf32(acc[m][n], al0, al1, al2, al3, bh[n][0], bh[n][1]);
                        mma_tf32(acc[m][n], ah0, ah1, ah2, ah3, bh[n][0], bh[n][1]);
                    }
                }
            }
        }

        // ---- epilogue: relu + layer-2 dot, reduce across warps ----
        float ep[4][2];
        #pragma unroll
        for (int m = 0; m < 4; m++) { ep[m][0] = 0.f; ep[m][1] = 0.f; }

        #pragma unroll
        for (int n = 0; n < 4; n++) {
            const int c0 = warp * 32 + n * 8 + 2 * lq;
            const float bb0 = sb1[c0],     bb1 = sb1[c0 + 1];
            const float ww0 = sw2[c0],     ww1 = sw2[c0 + 1];
            #pragma unroll
            for (int m = 0; m < 4; m++) {
                ep[m][0] += fmaxf(acc[m][n][0] + bb0, 0.f) * ww0
                          + fmaxf(acc[m][n][1] + bb1, 0.f) * ww1;
                ep[m][1] += fmaxf(acc[m][n][2] + bb0, 0.f) * ww0
                          + fmaxf(acc[m][n][3] + bb1, 0.f) * ww1;
            }
        }
        // reduce over the 4 lanes of each quad-group (they hold distinct cols)
        #pragma unroll
        for (int m = 0; m < 4; m++) {
            #pragma unroll
            for (int off = 1; off <= 2; off <<= 1) {
                ep[m][0] += __shfl_xor_sync(0xffffffffu, ep[m][0], off);
                ep[m][1] += __shfl_xor_sync(0xffffffffu, ep[m][1], off);
            }
        }
        if (lq == 0) {
            #pragma unroll
            for (int m = 0; m < 4; m++) {
                red[m * 16 + lg][warp]     = ep[m][0];
                red[m * 16 + lg + 8][warp] = ep[m][1];
            }
        }
        __syncthreads();

        if (tid < 64 && se[tid] >= 0) {
            float s = 0.f;
            #pragma unroll
            for (int w = 0; w < 8; w++) s += red[tid][w];
            out[se[tid]] = stv[tid] * (s + b2s);
        }
    }
}

// ---------------- kernel 6: aux loss reduction (deterministic) ----------------
__global__ __launch_bounds__(256) void k_aux(float* out, int out_size, int nblocks, int E)
{
    __shared__ float s[256];
    float acc[NEXP] = {0.f, 0.f, 0.f, 0.f};
    for (int i = threadIdx.x; i < nblocks; i += 256) {
        #pragma unroll
        for (int j = 0; j < NEXP; j++) acc[j] += g_partial[i][j];
    }
    float tot[NEXP];
    #pragma unroll
    for (int j = 0; j < NEXP; j++) {
        s[threadIdx.x] = acc[j];
        __syncthreads();
        for (int st = 128; st; st >>= 1) {
            if (threadIdx.x < st) s[threadIdx.x] += s[threadIdx.x + st];
            __syncthreads();
        }
        tot[j] = s[0];
        __syncthreads();
    }
    if (threadIdx.x == 0 && out_size > E) {
        float aux = 0.f;
        const float invE = 1.f / (float)E;
        #pragma unroll
        for (int j = 0; j < NEXP; j++) {
            const float m = tot[j] * invE;
            aux += m * m;
        }
        out[E] = aux * (float)NEXP;
    }
}

// ---------------- host launcher ----------------
extern "C" void kernel_launch(void* const* d_in, const int* in_sizes, int n_in,
                              void* d_out, int out_size)
{
    const float* z       = (const float*)d_in[0];
    const void*  u       = d_in[1];
    const void*  v       = d_in[2];
    const float* gate_w  = (const float*)d_in[3];
    const float* gate_b  = (const float*)d_in[4];
    const float* cat_w1  = (const float*)d_in[5];
    const float* cat_b1  = (const float*)d_in[6];
    const float* cat_w2  = (const float*)d_in[7];
    const float* cat_b2  = (const float*)d_in[8];
    const float* dist_w1 = (const float*)d_in[9];
    const float* dist_b1 = (const float*)d_in[10];
    const float* dist_w2 = (const float*)d_in[11];
    const float* dist_b2 = (const float*)d_in[12];
    const float* mul_w1  = (const float*)d_in[13];
    const float* mul_b1  = (const float*)d_in[14];
    const float* mul_w2  = (const float*)d_in[15];
    const float* mul_b2  = (const float*)d_in[16];
    const float* all_w1  = (const float*)d_in[17];
    const float* all_b1  = (const float*)d_in[18];
    const float* all_w2  = (const float*)d_in[19];
    const float* all_b2  = (const float*)d_in[20];
    float* out = (float*)d_out;

    const int E = in_sizes[1];                 // 262144
    const int gateBlocks = (E + 63) / 64;      // 4096

    k_init<<<1, 256>>>(u);
    k_gate<<<gateBlocks, 256>>>(z, u, v, gate_w, gate_b, E);

    k_expert<256, 0><<<1024, 256>>>(z, u, v, cat_w1,  cat_b1,  cat_w2,  cat_b2,  out, 0);
    k_expert<128, 1><<<1024, 256>>>(z, u, v, dist_w1, dist_b1, dist_w2, dist_b2, out, 1);
    k_expert<128, 2><<<1024, 256>>>(z, u, v, mul_w1,  mul_b1,  mul_w2,  mul_b2,  out, 2);
    k_expert<512, 3><<<1024, 256>>>(z, u, v, all_w1,  all_b1,  all_w2,  all_b2,  out, 3);

    k_aux<<<1, 256>>>(out, out_size, gateBlocks, E);
}

// round 3
// speedup vs baseline: 2.1692x; 1.4808x over previous
#include <cuda_runtime.h>
#include <cuda_bf16.h>
#include <math.h>
#include <stdint.h>

// Problem constants (fixed for this dataset)
#define NNODES 50000
#define MAXE   262144
#define DDIM   128
#define HDIM   256
#define NEXP   4

// ---------------- device scratch (static allocation only) ----------------
__device__ int   g_counts[NEXP];
__device__ int   g_flag64;
__device__ int   g_bucket[NEXP][MAXE];      // 4 MB
__device__ float g_topv[MAXE];              // 1 MB
__device__ float g_partial[4096][NEXP];     // per gate-block prob sums

// ---------------- helpers ----------------
__device__ __forceinline__ uint32_t f2tf32(float x) {
    uint32_t r;
    asm("cvt.rna.tf32.f32 %0, %1;" : "=r"(r) : "f"(x));
    return r;
}

__device__ __forceinline__ void split_tf32(float x, float& hi, float& lo) {
    uint32_t h = f2tf32(x);
    hi = __uint_as_float(h);
    lo = __uint_as_float(f2tf32(x - hi));
}

__device__ __forceinline__ void mma_tf32(float c[4],
                                         uint32_t a0, uint32_t a1, uint32_t a2, uint32_t a3,
                                         uint32_t b0, uint32_t b1) {
    asm volatile(
        "mma.sync.aligned.m16n8k8.row.col.f32.tf32.tf32.f32 "
        "{%0,%1,%2,%3}, {%4,%5,%6,%7}, {%8,%9}, {%0,%1,%2,%3};"
        : "+f"(c[0]), "+f"(c[1]), "+f"(c[2]), "+f"(c[3])
        : "r"(a0), "r"(a1), "r"(a2), "r"(a3), "r"(b0), "r"(b1));
}

__device__ __forceinline__ void cp_async16(uint32_t smem_addr, const void* gptr) {
    asm volatile("cp.async.cg.shared.global [%0], [%1], 16;\n"
                 :: "r"(smem_addr), "l"(gptr));
}
__device__ __forceinline__ void cp_async_commit() {
    asm volatile("cp.async.commit_group;\n");
}
__device__ __forceinline__ void cp_async_wait0() {
    asm volatile("cp.async.wait_group 0;\n");
}

// ---------------- kernel 0: init + index dtype sniff ----------------
__global__ void k_init(const void* uptr) {
    if (threadIdx.x < NEXP) g_counts[threadIdx.x] = 0;
    if (threadIdx.x == 0) {
        const int* p = (const int*)uptr;
        int is64 = 1;
        #pragma unroll 1
        for (int i = 0; i < 64; i++) {
            if (p[2 * i + 1] != 0) { is64 = 0; break; }
        }
        g_flag64 = is64;
    }
}

// ---------------- kernel 1: gate (softmax + top-1 + bucketing) ----------------
__global__ __launch_bounds__(256) void k_gate(
    const float* __restrict__ z,
    const void*  __restrict__ u_, const void* __restrict__ v_,
    const float* __restrict__ gate_w,   // [512,4] row-major
    const float* __restrict__ gate_b,   // [4]
    int E)
{
    __shared__ __align__(16) float sgw[512 * 4];
    __shared__ float wpart[8][NEXP];

    const int tid  = threadIdx.x;
    const int warp = tid >> 5;
    const int lane = tid & 31;

    for (int t = tid; t < 2048; t += 256) sgw[t] = gate_w[t];
    __syncthreads();

    const int flag64 = g_flag64;
    const float4* gw4 = reinterpret_cast<const float4*>(sgw);

    float p0 = 0.f, p1 = 0.f, p2 = 0.f, p3 = 0.f;

    #pragma unroll 1
    for (int t = 0; t < 8; t++) {
        const int e = (int)blockIdx.x * 64 + warp * 8 + t;
        if (e >= E) break;

        int uu, vv;
        if (flag64) {
            uu = (int)((const long long*)u_)[e];
            vv = (int)((const long long*)v_)[e];
        } else {
            uu = ((const int*)u_)[e];
            vv = ((const int*)v_)[e];
        }
        const float* zu = z + (size_t)uu * DDIM;
        const float* zv = z + (size_t)vv * DDIM;

        float g0 = 0.f, g1 = 0.f, g2 = 0.f, g3 = 0.f;
        #pragma unroll
        for (int kk = 0; kk < 4; kk++) {
            const int k = lane + kk * 32;
            const float a = zu[k];
            const float b = zv[k];
            const float d = fabsf(a - b);
            const float m = a * b;
            const float4 wA = gw4[k];
            const float4 wB = gw4[128 + k];
            const float4 wD = gw4[256 + k];
            const float4 wM = gw4[384 + k];
            g0 += a * wA.x + b * wB.x + d * wD.x + m * wM.x;
            g1 += a * wA.y + b * wB.y + d * wD.y + m * wM.y;
            g2 += a * wA.z + b * wB.z + d * wD.z + m * wM.z;
            g3 += a * wA.w + b * wB.w + d * wD.w + m * wM.w;
        }
        #pragma unroll
        for (int off = 16; off; off >>= 1) {
            g0 += __shfl_xor_sync(0xffffffffu, g0, off);
            g1 += __shfl_xor_sync(0xffffffffu, g1, off);
            g2 += __shfl_xor_sync(0xffffffffu, g2, off);
            g3 += __shfl_xor_sync(0xffffffffu, g3, off);
        }

        if (lane == 0) {
            float l[NEXP];
            l[0] = g0 + gate_b[0]; l[1] = g1 + gate_b[1];
            l[2] = g2 + gate_b[2]; l[3] = g3 + gate_b[3];
            float mx = l[0];
            #pragma unroll
            for (int j = 1; j < NEXP; j++) mx = fmaxf(mx, l[j]);
            float ex[NEXP]; float s = 0.f;
            #pragma unroll
            for (int j = 0; j < NEXP; j++) { ex[j] = expf(l[j] - mx); s += ex[j]; }
            const float inv = 1.f / s;
            float pr[NEXP];
            #pragma unroll
            for (int j = 0; j < NEXP; j++) pr[j] = ex[j] * inv;
            int arg = 0; float best = pr[0];
            #pragma unroll
            for (int j = 1; j < NEXP; j++) if (pr[j] > best) { best = pr[j]; arg = j; }

            g_topv[e] = best;
            const int pos = atomicAdd(&g_counts[arg], 1);
            g_bucket[arg][pos] = e;

            p0 += pr[0]; p1 += pr[1]; p2 += pr[2]; p3 += pr[3];
        }
    }

    if (lane == 0) {
        wpart[warp][0] = p0; wpart[warp][1] = p1;
        wpart[warp][2] = p2; wpart[warp][3] = p3;
    }
    __syncthreads();
    if (tid < NEXP) {
        float s = 0.f;
        #pragma unroll
        for (int w = 0; w < 8; w++) s += wpart[w][tid];
        g_partial[blockIdx.x][tid] = s;
    }
}

// ---------------- kernels 2-5: fused expert MLPs (tf32x2, double-buffered) --
// MODE: 0 = cat [zu,zv] K=256; 1 = dist K=128; 2 = mul K=128; 3 = all K=512
// 2-pass tf32: acc += Xhi*W + Xlo*W  (W single tf32-rounded at frag load)
// W streamed via cp.async (raw fp32), X via regs; two smem buffers, 1 sync/chunk.

#define KC      16
#define XSTR    72    // banks 8k+e -> conflict-free fragment loads
#define WSTR    264   // banks 8k+n -> conflict-free fragment loads
#define BUFSZ   (2 * KC * XSTR + KC * WSTR)   // floats: Xhi + Xlo + Wraw = 6528

template <int K, int MODE>
__global__ __launch_bounds__(256, 2) void k_expert(
    const float* __restrict__ z,
    const void*  __restrict__ u_, const void* __restrict__ v_,
    const float* __restrict__ w1,  // [K,256]
    const float* __restrict__ b1,  // [256]
    const float* __restrict__ w2,  // [256,1]
    const float* __restrict__ b2,  // [1]
    float* __restrict__ out,
    int expert)
{
    extern __shared__ __align__(16) float sm[];
    float* sb1 = sm + 2 * BUFSZ;        // [256]
    float* sw2 = sb1 + 256;             // [256]
    float* red = sw2 + 256;             // [64][8]
    float* stv = red + 512;             // [64]
    int*   se  = (int*)(stv + 64);      // [64]
    int*   su  = se + 64;               // [64]
    int*   sv  = su + 64;               // [64]

    const int tid  = threadIdx.x;
    const int warp = tid >> 5;
    const int lane = tid & 31;
    const int lq   = lane & 3;
    const int lg   = lane >> 2;

    if (tid < HDIM) { sb1[tid] = b1[tid]; sw2[tid] = w2[tid]; }
    const float b2s    = b2[0];
    const int   flag64 = g_flag64;
    const int   count  = g_counts[expert];
    const int   ntiles = (count + 63) >> 6;
    constexpr int NCH  = K / KC;

    // W cp.async mapping: 4 x 16B per thread per chunk
    int wr[4], wc[4];
    #pragma unroll
    for (int i = 0; i < 4; i++) {
        const int idx = tid + i * 256;
        wr[i] = idx >> 6;
        wc[i] = (idx & 63) << 2;
    }
    // X mapping: edge xe, dims xj..xj+3 within chunk
    const int xe = tid >> 2;
    const int xj = (tid & 3) << 2;

    for (int tile = blockIdx.x; tile < ntiles; tile += gridDim.x) {
        __syncthreads();   // guard smem reuse across tiles
        const int base = tile * 64;
        const int nE   = min(64, count - base);

        if (tid < 64) {
            int e = (tid < nE) ? g_bucket[expert][base + tid] : -1;
            se[tid]  = e;
            stv[tid] = (e >= 0) ? g_topv[e] : 0.f;
            int uu = 0, vv = 0;
            if (e >= 0) {
                if (flag64) {
                    uu = (int)((const long long*)u_)[e];
                    vv = (int)((const long long*)v_)[e];
                } else {
                    uu = ((const int*)u_)[e];
                    vv = ((const int*)v_)[e];
                }
            }
            su[tid] = uu; sv[tid] = vv;
        }
        __syncthreads();

        const float* zu = z + (size_t)su[xe] * DDIM;
        const float* zv = z + (size_t)sv[xe] * DDIM;

        float acc[4][4][4];
        #pragma unroll
        for (int m = 0; m < 4; m++)
            #pragma unroll
            for (int n = 0; n < 4; n++)
                #pragma unroll
                for (int q = 0; q < 4; q++) acc[m][n][q] = 0.f;

        // ---- prologue: chunk 0 into buffer 0 ----
        {
            float* bW = sm + 2 * KC * XSTR;
            #pragma unroll
            for (int i = 0; i < 4; i++) {
                const uint32_t dst = (uint32_t)__cvta_generic_to_shared(bW + wr[i] * WSTR + wc[i]);
                cp_async16(dst, w1 + (size_t)wr[i] * HDIM + wc[i]);
            }
            cp_async_commit();
            const float4 xa = *reinterpret_cast<const float4*>(zu + xj);
            const float4 xb = *reinterpret_cast<const float4*>(zv + xj);
            const float av[4] = { xa.x, xa.y, xa.z, xa.w };
            const float bv[4] = { xb.x, xb.y, xb.z, xb.w };
            #pragma unroll
            for (int i = 0; i < 4; i++) {
                float val;
                if (MODE == 0)      val = av[i];
                else if (MODE == 1) val = fabsf(av[i] - bv[i]);
                else if (MODE == 2) val = av[i] * bv[i];
                else                val = av[i];
                float hi, lo;
                split_tf32(val, hi, lo);
                sm[(xj + i) * XSTR + xe]             = hi;
                sm[KC * XSTR + (xj + i) * XSTR + xe] = lo;
            }
            cp_async_wait0();
        }
        __syncthreads();

        #pragma unroll 1
        for (int cb = 0; cb < NCH; cb++) {
            float* cur = sm + (cb & 1) * BUFSZ;
            float* nxt = sm + ((cb + 1) & 1) * BUFSZ;

            // ---- issue next-chunk loads (overlap with compute below) ----
            float4 xa, xb;
            const bool more = (cb + 1 < NCH);
            if (more) {
                const int kb2 = (cb + 1) * KC;
                float* bW = nxt + 2 * KC * XSTR;
                #pragma unroll
                for (int i = 0; i < 4; i++) {
                    const uint32_t dst = (uint32_t)__cvta_generic_to_shared(bW + wr[i] * WSTR + wc[i]);
                    cp_async16(dst, w1 + (size_t)(kb2 + wr[i]) * HDIM + wc[i]);
                }
                cp_async_commit();
                const int d0 = kb2 & 127;
                xa = *reinterpret_cast<const float4*>(zu + d0 + xj);
                xb = *reinterpret_cast<const float4*>(zv + d0 + xj);
            }

            // ---- tensor compute on current buffer ----
            const float* cXhi = cur;
            const float* cXlo = cur + KC * XSTR;
            const float* cW   = cur + 2 * KC * XSTR;

            #pragma unroll
            for (int k8 = 0; k8 < 2; k8++) {
                const int kr   = k8 * 8 + lq;
                const int ncol = warp * 32 + lg;

                uint32_t bh[4][2];
                #pragma unroll
                for (int n = 0; n < 4; n++) {
                    const int wi = kr * WSTR + ncol + n * 8;
                    bh[n][0] = f2tf32(cW[wi]);
                    bh[n][1] = f2tf32(cW[wi + 4 * WSTR]);
                }

                #pragma unroll
                for (int m = 0; m < 4; m++) {
                    const int xi = kr * XSTR + m * 16 + lg;
                    const uint32_t ah0 = __float_as_uint(cXhi[xi]);
                    const uint32_t ah1 = __float_as_uint(cXhi[xi + 8]);
                    const uint32_t ah2 = __float_as_uint(cXhi[xi + 4 * XSTR]);
                    const uint32_t ah3 = __float_as_uint(cXhi[xi + 4 * XSTR + 8]);
                    const uint32_t al0 = __float_as_uint(cXlo[xi]);
                    const uint32_t al1 = __float_as_uint(cXlo[xi + 8]);
                    const uint32_t al2 = __float_as_uint(cXlo[xi + 4 * XSTR]);
                    const uint32_t al3 = __float_as_uint(cXlo[xi + 4 * XSTR + 8]);

                    #pragma unroll
                    for (int n = 0; n < 4; n++) {
                        mma_tf32(acc[m][n], al0, al1, al2, al3, bh[n][0], bh[n][1]);
                        mma_tf32(acc[m][n], ah0, ah1, ah2, ah3, bh[n][0], bh[n][1]);
                    }
                }
            }

            // ---- store next-chunk X into alternate buffer ----
            if (more) {
                const int type = ((cb + 1) * KC) >> 7;
                const float av[4] = { xa.x, xa.y, xa.z, xa.w };
                const float bv[4] = { xb.x, xb.y, xb.z, xb.w };
                #pragma unroll
                for (int i = 0; i < 4; i++) {
                    float val;
                    if (MODE == 0)      val = (type == 0) ? av[i] : bv[i];
                    else if (MODE == 1) val = fabsf(av[i] - bv[i]);
                    else if (MODE == 2) val = av[i] * bv[i];
                    else {
                        if (type == 0)      val = av[i];
                        else if (type == 1) val = bv[i];
                        else if (type == 2) val = fabsf(av[i] - bv[i]);
                        else                val = av[i] * bv[i];
                    }
                    float hi, lo;
                    split_tf32(val, hi, lo);
                    nxt[(xj + i) * XSTR + xe]             = hi;
                    nxt[KC * XSTR + (xj + i) * XSTR + xe] = lo;
                }
            }
            cp_async_wait0();
            __syncthreads();
        }

        // ---- epilogue: relu + layer-2 dot, reduce ----
        float ep[4][2];
        #pragma unroll
        for (int m = 0; m < 4; m++) { ep[m][0] = 0.f; ep[m][1] = 0.f; }

        #pragma unroll
        for (int n = 0; n < 4; n++) {
            const int c0 = warp * 32 + n * 8 + 2 * lq;
            const float bb0 = sb1[c0],     bb1 = sb1[c0 + 1];
            const float ww0 = sw2[c0],     ww1 = sw2[c0 + 1];
            #pragma unroll
            for (int m = 0; m < 4; m++) {
                ep[m][0] += fmaxf(acc[m][n][0] + bb0, 0.f) * ww0
                          + fmaxf(acc[m][n][1] + bb1, 0.f) * ww1;
                ep[m][1] += fmaxf(acc[m][n][2] + bb0, 0.f) * ww0
                          + fmaxf(acc[m][n][3] + bb1, 0.f) * ww1;
            }
        }
        #pragma unroll
        for (int m = 0; m < 4; m++) {
            #pragma unroll
            for (int off = 1; off <= 2; off <<= 1) {
                ep[m][0] += __shfl_xor_sync(0xffffffffu, ep[m][0], off);
                ep[m][1] += __shfl_xor_sync(0xffffffffu, ep[m][1], off);
            }
        }
        if (lq == 0) {
            #pragma unroll
            for (int m = 0; m < 4; m++) {
                red[(m * 16 + lg) * 8 + warp]       = ep[m][0];
                red[(m * 16 + lg + 8) * 8 + warp]   = ep[m][1];
            }
        }
        __syncthreads();

        if (tid < 64 && se[tid] >= 0) {
            float s = 0.f;
            #pragma unroll
            for (int w = 0; w < 8; w++) s += red[tid * 8 + w];
            out[se[tid]] = stv[tid] * (s + b2s);
        }
    }
}

// ---------------- kernel 6: aux loss reduction (deterministic) ----------------
__global__ __launch_bounds__(256) void k_aux(float* out, int out_size, int nblocks, int E)
{
    __shared__ float s[256];
    float acc[NEXP] = {0.f, 0.f, 0.f, 0.f};
    for (int i = threadIdx.x; i < nblocks; i += 256) {
        #pragma unroll
        for (int j = 0; j < NEXP; j++) acc[j] += g_partial[i][j];
    }
    float tot[NEXP];
    #pragma unroll
    for (int j = 0; j < NEXP; j++) {
        s[threadIdx.x] = acc[j];
        __syncthreads();
        for (int st = 128; st; st >>= 1) {
            if (threadIdx.x < st) s[threadIdx.x] += s[threadIdx.x + st];
            __syncthreads();
        }
        tot[j] = s[0];
        __syncthreads();
    }
    if (threadIdx.x == 0 && out_size > E) {
        float aux = 0.f;
        const float invE = 1.f / (float)E;
        #pragma unroll
        for (int j = 0; j < NEXP; j++) {
            const float m = tot[j] * invE;
            aux += m * m;
        }
        out[E] = aux * (float)NEXP;
    }
}

// ---------------- host launcher ----------------
#define EXP_SMEM ((2 * BUFSZ + 256 + 256 + 512 + 64 + 192) * 4)

extern "C" void kernel_launch(void* const* d_in, const int* in_sizes, int n_in,
                              void* d_out, int out_size)
{
    const float* z       = (const float*)d_in[0];
    const void*  u       = d_in[1];
    const void*  v       = d_in[2];
    const float* gate_w  = (const float*)d_in[3];
    const float* gate_b  = (const float*)d_in[4];
    const float* cat_w1  = (const float*)d_in[5];
    const float* cat_b1  = (const float*)d_in[6];
    const float* cat_w2  = (const float*)d_in[7];
    const float* cat_b2  = (const float*)d_in[8];
    const float* dist_w1 = (const float*)d_in[9];
    const float* dist_b1 = (const float*)d_in[10];
    const float* dist_w2 = (const float*)d_in[11];
    const float* dist_b2 = (const float*)d_in[12];
    const float* mul_w1  = (const float*)d_in[13];
    const float* mul_b1  = (const float*)d_in[14];
    const float* mul_w2  = (const float*)d_in[15];
    const float* mul_b2  = (const float*)d_in[16];
    const float* all_w1  = (const float*)d_in[17];
    const float* all_b1  = (const float*)d_in[18];
    const float* all_w2  = (const float*)d_in[19];
    const float* all_b2  = (const float*)d_in[20];
    float* out = (float*)d_out;

    const int E = in_sizes[1];                 // 262144
    const int gateBlocks = (E + 63) / 64;      // 4096

    cudaFuncSetAttribute(k_expert<256, 0>, cudaFuncAttributeMaxDynamicSharedMemorySize, EXP_SMEM);
    cudaFuncSetAttribute(k_expert<128, 1>, cudaFuncAttributeMaxDynamicSharedMemorySize, EXP_SMEM);
    cudaFuncSetAttribute(k_expert<128, 2>, cudaFuncAttributeMaxDynamicSharedMemorySize, EXP_SMEM);
    cudaFuncSetAttribute(k_expert<512, 3>, cudaFuncAttributeMaxDynamicSharedMemorySize, EXP_SMEM);

    k_init<<<1, 256>>>(u);
    k_gate<<<gateBlocks, 256>>>(z, u, v, gate_w, gate_b, E);

    k_expert<256, 0><<<1024, 256, EXP_SMEM>>>(z, u, v, cat_w1,  cat_b1,  cat_w2,  cat_b2,  out, 0);
    k_expert<128, 1><<<1024, 256, EXP_SMEM>>>(z, u, v, dist_w1, dist_b1, dist_w2, dist_b2, out, 1);
    k_expert<128, 2><<<1024, 256, EXP_SMEM>>>(z, u, v, mul_w1,  mul_b1,  mul_w2,  mul_b2,  out, 2);
    k_expert<512, 3><<<1024, 256, EXP_SMEM>>>(z, u, v, all_w1,  all_b1,  all_w2,  all_b2,  out, 3);

    k_aux<<<1, 256>>>(out, out_size, gateBlocks, E);
}